// round 10
// baseline (speedup 1.0000x reference)
#include <cuda_runtime.h>
#include <cuda_bf16.h>
#include <cstdint>

#define N_NODES 200000
#define N_EDGES 800000
#define D 128
#define NT 1563            // ceil(200000/128); last tile has 64 valid rows
#define NCONS 128
#define NPROD 20
#define GRID_FUSED (NCONS + NPROD)
#define SCAN_BLKS 196      // ceil(200000/1024)

// ---------------------------------------------------------------------------
// Device scratch (allocation-free rule).
// ---------------------------------------------------------------------------
__device__ float g_agg[(size_t)N_NODES * D];
__device__ int g_ready[NT];
// CSR for edge->receiver gather
__device__ int g_hist[N_NODES];
__device__ int g_off[N_NODES + 1];
__device__ int g_cur[N_NODES];
__device__ int g_elist[N_EDGES];
__device__ int g_bsum[256];
__device__ int g_boff[256];
// Fragment-major weights: uint4 = {hi_b0, hi_b1, lo_b0, lo_b1} per (nb, ks, lane)
__device__ uint4 g_W1f[16 * 16 * 32];   // [nb][ksg 0..15][lane]
__device__ uint4 g_W2f[16 * 8 * 32];    // [nb][ksg 0..7][lane]

// ---------------------------------------------------------------------------
// helpers
// ---------------------------------------------------------------------------
__device__ __forceinline__ uint32_t smem_u32(const void* p) {
    uint32_t a;
    asm("{ .reg .u64 t; cvta.to.shared.u64 t, %1; cvt.u32.u64 %0, t; }"
        : "=r"(a) : "l"(p));
    return a;
}
__device__ __forceinline__ uint32_t pack_bf16x2(float lo, float hi) {
    uint32_t r;
    asm("cvt.rn.bf16x2.f32 %0, %1, %2;" : "=r"(r) : "f"(hi), "f"(lo));
    return r;
}
__device__ __forceinline__ void split2(float v0, float v1,
                                       uint32_t& hp, uint32_t& lp) {
    hp = pack_bf16x2(v0, v1);
    float h0 = __uint_as_float(hp << 16);
    float h1 = __uint_as_float(hp & 0xffff0000u);
    lp = pack_bf16x2(v0 - h0, v1 - h1);
}
__device__ __forceinline__ void ldsm_x4(uint32_t (&r)[4], uint32_t addr) {
    asm volatile("ldmatrix.sync.aligned.m8n8.x4.shared.b16 {%0,%1,%2,%3}, [%4];"
                 : "=r"(r[0]), "=r"(r[1]), "=r"(r[2]), "=r"(r[3]) : "r"(addr));
}
__device__ __forceinline__ void mma_bf16(float (&d)[4], const uint32_t (&a)[4],
                                         uint32_t b0, uint32_t b1) {
    asm volatile(
        "mma.sync.aligned.m16n8k16.row.col.f32.bf16.bf16.f32 "
        "{%0,%1,%2,%3}, {%4,%5,%6,%7}, {%8,%9}, {%0,%1,%2,%3};"
        : "+f"(d[0]), "+f"(d[1]), "+f"(d[2]), "+f"(d[3])
        : "r"(a[0]), "r"(a[1]), "r"(a[2]), "r"(a[3]), "r"(b0), "r"(b1));
}
__device__ __forceinline__ void cp_async16(uint32_t dst, const void* src) {
    asm volatile("cp.async.ca.shared.global [%0], [%1], 16;"
                 :: "r"(dst), "l"(src) : "memory");
}
#define CP_COMMIT() asm volatile("cp.async.commit_group;" ::: "memory")
#define CP_WAIT0()  asm volatile("cp.async.wait_group 0;" ::: "memory")

// ---------------------------------------------------------------------------
// Kernel 0: fragment-major hi/lo bf16 weights.
// ---------------------------------------------------------------------------
__global__ void prep_w_kernel(const float* __restrict__ W1,
                              const float* __restrict__ W2) {
    int i = blockIdx.x * blockDim.x + threadIdx.x;
    if (i < 8192) {                       // W1: 16 nb x 16 ks x 32 lanes
        int lane = i & 31, ks = (i >> 5) & 15, nb = i >> 9;
        int n = nb * 8 + (lane >> 2);
        int k0 = ks * 16 + 2 * (lane & 3);
        float v00 = W1[(k0 + 0) * 128 + n], v01 = W1[(k0 + 1) * 128 + n];
        float v10 = W1[(k0 + 8) * 128 + n], v11 = W1[(k0 + 9) * 128 + n];
        uint32_t hb0, lb0, hb1, lb1;
        split2(v00, v01, hb0, lb0);
        split2(v10, v11, hb1, lb1);
        g_W1f[i] = make_uint4(hb0, hb1, lb0, lb1);
    }
    if (i < 4096) {                       // W2: 16 nb x 8 ks x 32 lanes
        int lane = i & 31, ks = (i >> 5) & 7, nb = i >> 8;
        int n = nb * 8 + (lane >> 2);
        int k0 = ks * 16 + 2 * (lane & 3);
        float v00 = W2[(k0 + 0) * 128 + n], v01 = W2[(k0 + 1) * 128 + n];
        float v10 = W2[(k0 + 8) * 128 + n], v11 = W2[(k0 + 9) * 128 + n];
        uint32_t hb0, lb0, hb1, lb1;
        split2(v00, v01, hb0, lb0);
        split2(v10, v11, hb1, lb1);
        g_W2f[i] = make_uint4(hb0, hb1, lb0, lb1);
    }
}

// ---------------------------------------------------------------------------
// CSR build: zero (hist + ready flags) -> histogram -> scan -> fill.
// ---------------------------------------------------------------------------
__global__ void zero_hist_kernel() {
    int i = blockIdx.x * 1024 + threadIdx.x;
    if (i < N_NODES) g_hist[i] = 0;
    if (i < NT) g_ready[i] = 0;
}
__global__ void hist_kernel(const int* __restrict__ recv) {
    int e = blockIdx.x * blockDim.x + threadIdx.x;
    if (e < N_EDGES) atomicAdd(&g_hist[recv[e]], 1);
}
__global__ void scan1_kernel() {
    __shared__ int s[1024];
    int t = threadIdx.x;
    int i = blockIdx.x * 1024 + t;
    int v = (i < N_NODES) ? g_hist[i] : 0;
    s[t] = v;
    __syncthreads();
    #pragma unroll
    for (int d = 1; d < 1024; d <<= 1) {
        int a = (t >= d) ? s[t - d] : 0;
        __syncthreads();
        s[t] += a;
        __syncthreads();
    }
    if (i < N_NODES) g_off[i] = s[t] - v;
    if (t == 1023) g_bsum[blockIdx.x] = s[t];
}
__global__ void scan2_kernel() {
    __shared__ int s[256];
    int t = threadIdx.x;
    int v = (t < SCAN_BLKS) ? g_bsum[t] : 0;
    s[t] = v;
    __syncthreads();
    #pragma unroll
    for (int d = 1; d < 256; d <<= 1) {
        int a = (t >= d) ? s[t - d] : 0;
        __syncthreads();
        s[t] += a;
        __syncthreads();
    }
    g_boff[t] = s[t] - v;
}
__global__ void scan3_kernel() {
    int i = blockIdx.x * 1024 + threadIdx.x;
    if (i < N_NODES) {
        int o = g_off[i] + g_boff[blockIdx.x];
        g_off[i] = o;
        g_cur[i] = o;
    }
    if (i == 0) g_off[N_NODES] = N_EDGES;
}
__global__ void fill_kernel(const int* __restrict__ recv) {
    int e = blockIdx.x * blockDim.x + threadIdx.x;
    if (e < N_EDGES) {
        int pos = atomicAdd(&g_cur[recv[e]], 1);
        g_elist[pos] = e;
    }
}

// ---------------------------------------------------------------------------
// Fused persistent kernel: 128 consumer CTAs (MLP) + 20 producer CTAs (gather).
// ---------------------------------------------------------------------------
#define PITCH 136
#define AB_B  (128 * PITCH * 2)          // 34816
#define OFF_A0HI 0
#define OFF_A0LO (OFF_A0HI + AB_B)
#define OFF_A1HI (OFF_A0LO + AB_B)
#define OFF_A1LO (OFF_A1HI + AB_B)
#define OFF_STG  (OFF_A1LO + AB_B)       // fp32 128x128 = 65536
#define OFF_B1   (OFF_STG + 65536)
#define OFF_B2   (OFF_B1 + 512)
#define SMEM_SZ  (OFF_B2 + 512)          // 205824

__global__ __launch_bounds__(512, 1) void fused_kernel(
    const float* __restrict__ x,
    const float* __restrict__ edge_attr,
    const float* __restrict__ b1,
    const float* __restrict__ b2,
    float* __restrict__ out) {

    extern __shared__ char smem[];
    const uint32_t sb = smem_u32(smem);
    const int tid = threadIdx.x;
    const int lane = tid & 31;
    const int w = tid >> 5;

    // ===================== PRODUCER CTAs: gather agg tiles =====================
    if (blockIdx.x >= NCONS) {
        const int p = blockIdx.x - NCONS;
        for (int tile = p; tile < NT; tile += NPROD) {
            const int node0 = tile * 128;
            const int V = min(128, N_NODES - node0);
            const int rbase = w * 8;                // warp rows rbase..rbase+7
            float4 a[8];
            #pragma unroll
            for (int q = 0; q < 8; ++q) a[q] = make_float4(0.f, 0.f, 0.f, 0.f);

            // lane<8 loads offsets for its node
            int off0 = 0, deg = 0;
            if (lane < 8) {
                int r = rbase + lane;
                if (r < V) {
                    int n = node0 + r;
                    off0 = __ldg(&g_off[n]);
                    deg  = __ldg(&g_off[n + 1]) - off0;
                }
            }
            int maxdeg = __reduce_max_sync(0xffffffffu, (lane < 8) ? deg : 0);

            for (int s = 0; s < maxdeg; s += 4) {
                // lane j: node j>>2, slot s+(j&3)
                int nn = lane >> 2, sl = s + (lane & 3);
                int o0n = __shfl_sync(0xffffffffu, off0, nn);
                int dn  = __shfl_sync(0xffffffffu, deg,  nn);
                int eid = (sl < dn) ? __ldg(&g_elist[o0n + sl]) : -1;
                #pragma unroll
                for (int q = 0; q < 8; ++q) {
                    #pragma unroll
                    for (int s2 = 0; s2 < 4; ++s2) {
                        int e = __shfl_sync(0xffffffffu, eid, q * 4 + s2);
                        if (e >= 0) {
                            float4 v = __ldg((const float4*)edge_attr +
                                             (size_t)e * 32 + lane);
                            a[q].x += v.x; a[q].y += v.y;
                            a[q].z += v.z; a[q].w += v.w;
                        }
                    }
                }
            }
            #pragma unroll
            for (int q = 0; q < 8; ++q) {
                int r = rbase + q;
                if (r < V)
                    ((float4*)g_agg)[(size_t)(node0 + r) * 32 + lane] = a[q];
            }
            __threadfence();
            __syncthreads();
            if (tid == 0) atomicExch(&g_ready[tile], 1);
        }
        return;
    }

    // ===================== CONSUMER CTAs: MLP =====================
    const int mw = (w & 3) * 32;
    const int nwb = (w >> 2) * 4;

    float* sB1 = (float*)(smem + OFF_B1);
    float* sB2 = (float*)(smem + OFF_B2);
    if (tid < 128) { sB1[tid] = b1[tid]; sB2[tid] = b2[tid]; }

    const int arow = lane & 15;
    const int acol = (lane >> 4) * 8;
    const int gr = tid >> 5;
    const int gc = tid & 31;

    float acc[2][4][4];
    #pragma unroll
    for (int mt = 0; mt < 2; ++mt)
        #pragma unroll
        for (int nt = 0; nt < 4; ++nt)
            #pragma unroll
            for (int e = 0; e < 4; ++e) acc[mt][nt][e] = 0.f;

    auto stage_load = [&](const float* src, int node0, int V) {
        #pragma unroll
        for (int j = 0; j < 8; ++j) {
            int r = gr + j * 16;
            int rr = (r < V) ? r : (V - 1);
            cp_async16(sb + OFF_STG + (uint32_t)(r * 128 + gc * 4) * 4,
                       src + (size_t)(node0 + rr) * 128 + gc * 4);
        }
        CP_COMMIT();
    };
    auto convert_stage = [&](uint32_t dhi, uint32_t dlo) {
        #pragma unroll
        for (int j = 0; j < 8; ++j) {
            int r = gr + j * 16;
            float4 v = *(const float4*)(smem + OFF_STG + (r * 128 + gc * 4) * 4);
            uint32_t h0, l0, h1, l1;
            split2(v.x, v.y, h0, l0);
            split2(v.z, v.w, h1, l1);
            uint32_t off = (uint32_t)(r * PITCH + gc * 4) * 2;
            asm volatile("st.shared.v2.u32 [%0], {%1, %2};"
                         :: "r"(dhi + off), "r"(h0), "r"(h1));
            asm volatile("st.shared.v2.u32 [%0], {%1, %2};"
                         :: "r"(dlo + off), "r"(l0), "r"(l1));
        }
    };
    auto mma_step = [&](uint32_t ahiB, uint32_t aloB, const uint4* wf,
                        int ksg, int nks) {
        uint32_t ahi[2][4], alo[2][4];
        #pragma unroll
        for (int mt = 0; mt < 2; ++mt) {
            uint32_t aoff = (uint32_t)((mw + mt * 16 + arow) * PITCH +
                                       (ksg & 7) * 16 + acol) * 2;
            ldsm_x4(ahi[mt], ahiB + aoff);
            ldsm_x4(alo[mt], aloB + aoff);
        }
        #pragma unroll
        for (int nt = 0; nt < 4; ++nt) {
            uint4 f = __ldg(&wf[((nwb + nt) * nks + ksg) * 32 + lane]);
            #pragma unroll
            for (int mt = 0; mt < 2; ++mt) {
                mma_bf16(acc[mt][nt], ahi[mt], f.x, f.y);
                mma_bf16(acc[mt][nt], alo[mt], f.x, f.y);
                mma_bf16(acc[mt][nt], ahi[mt], f.z, f.w);
            }
        }
    };

    int tile = blockIdx.x;
    if (tile < NT) stage_load(x, tile * 128, min(128, N_NODES - tile * 128));
    __syncthreads();   // biases visible

    for (; tile < NT; tile += NCONS) {
        const int node0 = tile * 128;
        const int V = min(128, N_NODES - node0);
        const int tile_n = tile + NCONS;
        const int node0n = (tile_n < NT) ? tile_n * 128 : 0;
        const int Vn = (tile_n < NT) ? min(128, N_NODES - node0n) : 128;

        CP_WAIT0();
        convert_stage(sb + OFF_A0HI, sb + OFF_A0LO);
        // wait for producer's agg tile
        if (tid == 0) {
            while (atomicAdd(&g_ready[tile], 0) == 0) __nanosleep(64);
        }
        __threadfence();
        __syncthreads();                        // A0 visible + flag seen
        stage_load(g_agg, node0, V);            // agg -> stage (async)

        #pragma unroll
        for (int ks = 0; ks < 4; ++ks)
            mma_step(sb + OFF_A0HI, sb + OFF_A0LO, g_W1f, ks, 16);
        CP_WAIT0();
        convert_stage(sb + OFF_A1HI, sb + OFF_A1LO);
        stage_load(x, node0n, Vn);
        #pragma unroll
        for (int ks = 4; ks < 8; ++ks)
            mma_step(sb + OFF_A0HI, sb + OFF_A0LO, g_W1f, ks, 16);
        __syncthreads();                        // A1 visible

        #pragma unroll
        for (int ks = 0; ks < 8; ++ks)
            mma_step(sb + OFF_A1HI, sb + OFF_A1LO, g_W1f, 8 + ks, 16);

        // Epilogue 1: H = relu(acc + b1) -> A0 buffers
        {
            const int r0 = lane >> 2;
            const int c0 = 2 * (lane & 3);
            #pragma unroll
            for (int mt = 0; mt < 2; ++mt) {
                #pragma unroll
                for (int nt = 0; nt < 4; ++nt) {
                    int c = nwb * 8 + nt * 8 + c0;
                    float bb0 = sB1[c], bb1 = sB1[c + 1];
                    int rA = mw + mt * 16 + r0;
                    float h00 = fmaxf(acc[mt][nt][0] + bb0, 0.f);
                    float h01 = fmaxf(acc[mt][nt][1] + bb1, 0.f);
                    float h10 = fmaxf(acc[mt][nt][2] + bb0, 0.f);
                    float h11 = fmaxf(acc[mt][nt][3] + bb1, 0.f);
                    uint32_t hp0, lp0, hp1, lp1;
                    split2(h00, h01, hp0, lp0);
                    split2(h10, h11, hp1, lp1);
                    uint32_t o0 = (uint32_t)(rA * PITCH + c) * 2;
                    uint32_t o1 = (uint32_t)((rA + 8) * PITCH + c) * 2;
                    asm volatile("st.shared.b32 [%0], %1;" :: "r"(sb + OFF_A0HI + o0), "r"(hp0));
                    asm volatile("st.shared.b32 [%0], %1;" :: "r"(sb + OFF_A0LO + o0), "r"(lp0));
                    asm volatile("st.shared.b32 [%0], %1;" :: "r"(sb + OFF_A0HI + o1), "r"(hp1));
                    asm volatile("st.shared.b32 [%0], %1;" :: "r"(sb + OFF_A0LO + o1), "r"(lp1));
                    #pragma unroll
                    for (int e = 0; e < 4; ++e) acc[mt][nt][e] = 0.f;
                }
            }
        }
        __syncthreads();                        // H visible

        #pragma unroll
        for (int ks = 0; ks < 8; ++ks)
            mma_step(sb + OFF_A0HI, sb + OFF_A0LO, g_W2f, ks, 8);

        // Epilogue 2: out = acc + b2
        {
            const int r0 = lane >> 2;
            const int c0 = 2 * (lane & 3);
            #pragma unroll
            for (int mt = 0; mt < 2; ++mt) {
                #pragma unroll
                for (int nt = 0; nt < 4; ++nt) {
                    int c = nwb * 8 + nt * 8 + c0;
                    float bb0 = sB2[c], bb1 = sB2[c + 1];
                    int r = mw + mt * 16 + r0;
                    if (r < V)
                        *(float2*)(out + (size_t)(node0 + r) * 128 + c) =
                            make_float2(acc[mt][nt][0] + bb0, acc[mt][nt][1] + bb1);
                    if (r + 8 < V)
                        *(float2*)(out + (size_t)(node0 + r + 8) * 128 + c) =
                            make_float2(acc[mt][nt][2] + bb0, acc[mt][nt][3] + bb1);
                    #pragma unroll
                    for (int e = 0; e < 4; ++e) acc[mt][nt][e] = 0.f;
                }
            }
        }
        __syncthreads();   // all reads of A0/A1 done before next tile writes
    }
}

// ---------------------------------------------------------------------------
extern "C" void kernel_launch(void* const* d_in, const int* in_sizes, int n_in,
                              void* d_out, int out_size) {
    const float* x          = (const float*)d_in[0];
    const float* edge_attr  = (const float*)d_in[1];
    const int*   edge_index = (const int*)d_in[2];   // int32
    const float* W1         = (const float*)d_in[3];
    const float* b1         = (const float*)d_in[4];
    const float* W2         = (const float*)d_in[5];
    const float* b2         = (const float*)d_in[6];
    float*       out        = (float*)d_out;

    const int* recv = edge_index + N_EDGES;

    cudaFuncSetAttribute(fused_kernel,
                         cudaFuncAttributeMaxDynamicSharedMemorySize, SMEM_SZ);

    prep_w_kernel<<<32, 256>>>(W1, W2);
    zero_hist_kernel<<<SCAN_BLKS, 1024>>>();
    hist_kernel<<<3125, 256>>>(recv);
    scan1_kernel<<<SCAN_BLKS, 1024>>>();
    scan2_kernel<<<1, 256>>>();
    scan3_kernel<<<SCAN_BLKS, 1024>>>();
    fill_kernel<<<3125, 256>>>(recv);
    fused_kernel<<<GRID_FUSED, 512, SMEM_SZ>>>(x, edge_attr, b1, b2, out);
}

// round 12
// speedup vs baseline: 2.0377x; 2.0377x over previous
#include <cuda_runtime.h>
#include <cuda_bf16.h>
#include <cstdint>

#define N_NODES 200000
#define N_EDGES 800000
#define D 128
#define NT 1563            // ceil(200000/128); last tile has 64 valid rows
#define GRID_MLP 148
#define SCAN_BLKS 196      // ceil(200000/1024)

// ---------------------------------------------------------------------------
// Device scratch (allocation-free rule).
// ---------------------------------------------------------------------------
__device__ __nv_bfloat16 g_xhi[(size_t)N_NODES * D];
__device__ __nv_bfloat16 g_xlo[(size_t)N_NODES * D];
__device__ __nv_bfloat16 g_ahi[(size_t)N_NODES * D];
__device__ __nv_bfloat16 g_alo[(size_t)N_NODES * D];
// CSR for edge->receiver gather
__device__ int g_hist[N_NODES];
__device__ int g_off[N_NODES + 1];
__device__ int g_cur[N_NODES];
__device__ int g_elist[N_EDGES];
__device__ int g_bsum[256];
__device__ int g_boff[256];
// Fragment-major weights: uint4 = {hi_b0, hi_b1, lo_b0, lo_b1} per (nb, ks, lane)
__device__ uint4 g_W1f[16 * 16 * 32];   // [nb][ksg 0..15][lane]
__device__ uint4 g_W2f[16 * 8 * 32];    // [nb][ksg 0..7][lane]

// ---------------------------------------------------------------------------
// helpers
// ---------------------------------------------------------------------------
__device__ __forceinline__ uint32_t smem_u32(const void* p) {
    uint32_t a;
    asm("{ .reg .u64 t; cvta.to.shared.u64 t, %1; cvt.u32.u64 %0, t; }"
        : "=r"(a) : "l"(p));
    return a;
}
__device__ __forceinline__ uint32_t pack_bf16x2(float lo, float hi) {
    uint32_t r;
    asm("cvt.rn.bf16x2.f32 %0, %1, %2;" : "=r"(r) : "f"(hi), "f"(lo));
    return r;
}
__device__ __forceinline__ void split2(float v0, float v1,
                                       uint32_t& hp, uint32_t& lp) {
    hp = pack_bf16x2(v0, v1);
    float h0 = __uint_as_float(hp << 16);
    float h1 = __uint_as_float(hp & 0xffff0000u);
    lp = pack_bf16x2(v0 - h0, v1 - h1);
}
__device__ __forceinline__ void ldsm_x4(uint32_t (&r)[4], uint32_t addr) {
    asm volatile("ldmatrix.sync.aligned.m8n8.x4.shared.b16 {%0,%1,%2,%3}, [%4];"
                 : "=r"(r[0]), "=r"(r[1]), "=r"(r[2]), "=r"(r[3]) : "r"(addr));
}
__device__ __forceinline__ void mma_bf16(float (&d)[4], const uint32_t (&a)[4],
                                         uint32_t b0, uint32_t b1) {
    asm volatile(
        "mma.sync.aligned.m16n8k16.row.col.f32.bf16.bf16.f32 "
        "{%0,%1,%2,%3}, {%4,%5,%6,%7}, {%8,%9}, {%0,%1,%2,%3};"
        : "+f"(d[0]), "+f"(d[1]), "+f"(d[2]), "+f"(d[3])
        : "r"(a[0]), "r"(a[1]), "r"(a[2]), "r"(a[3]), "r"(b0), "r"(b1));
}
__device__ __forceinline__ void cp_async16(uint32_t dst, const void* src) {
    asm volatile("cp.async.ca.shared.global [%0], [%1], 16;"
                 :: "r"(dst), "l"(src) : "memory");
}
#define CP_COMMIT() asm volatile("cp.async.commit_group;" ::: "memory")
#define CP_WAIT1()  asm volatile("cp.async.wait_group 1;" ::: "memory")

// ---------------------------------------------------------------------------
// Kernel 0: fragment-major hi/lo bf16 weights.
// ---------------------------------------------------------------------------
__global__ void prep_w_kernel(const float* __restrict__ W1,
                              const float* __restrict__ W2) {
    int i = blockIdx.x * blockDim.x + threadIdx.x;
    if (i < 8192) {                       // W1: 16 nb x 16 ks x 32 lanes
        int lane = i & 31, ks = (i >> 5) & 15, nb = i >> 9;
        int n = nb * 8 + (lane >> 2);
        int k0 = ks * 16 + 2 * (lane & 3);
        float v00 = W1[(k0 + 0) * 128 + n], v01 = W1[(k0 + 1) * 128 + n];
        float v10 = W1[(k0 + 8) * 128 + n], v11 = W1[(k0 + 9) * 128 + n];
        uint32_t hb0, lb0, hb1, lb1;
        split2(v00, v01, hb0, lb0);
        split2(v10, v11, hb1, lb1);
        g_W1f[i] = make_uint4(hb0, hb1, lb0, lb1);
    }
    if (i < 4096) {                       // W2: 16 nb x 8 ks x 32 lanes
        int lane = i & 31, ks = (i >> 5) & 7, nb = i >> 8;
        int n = nb * 8 + (lane >> 2);
        int k0 = ks * 16 + 2 * (lane & 3);
        float v00 = W2[(k0 + 0) * 128 + n], v01 = W2[(k0 + 1) * 128 + n];
        float v10 = W2[(k0 + 8) * 128 + n], v11 = W2[(k0 + 9) * 128 + n];
        uint32_t hb0, lb0, hb1, lb1;
        split2(v00, v01, hb0, lb0);
        split2(v10, v11, hb1, lb1);
        g_W2f[i] = make_uint4(hb0, hb1, lb0, lb1);
    }
}

// ---------------------------------------------------------------------------
// Kernel 0b: x fp32 -> bf16 hi/lo.
// ---------------------------------------------------------------------------
__global__ void prep_x_kernel(const float* __restrict__ x) {
    size_t i = (size_t)blockIdx.x * blockDim.x + threadIdx.x;
    if (i >= (size_t)N_NODES * 32) return;
    float4 v = ((const float4*)x)[i];
    uint32_t h0, l0, h1, l1;
    split2(v.x, v.y, h0, l0);
    split2(v.z, v.w, h1, l1);
    ((uint2*)g_xhi)[i] = make_uint2(h0, h1);
    ((uint2*)g_xlo)[i] = make_uint2(l0, l1);
}

// ---------------------------------------------------------------------------
// CSR build: zero hist -> histogram -> scan -> fill.
// ---------------------------------------------------------------------------
__global__ void zero_hist_kernel() {
    int i = blockIdx.x * 1024 + threadIdx.x;
    if (i < N_NODES) g_hist[i] = 0;
}
__global__ void hist_kernel(const int* __restrict__ recv) {
    int e = blockIdx.x * blockDim.x + threadIdx.x;
    if (e < N_EDGES) atomicAdd(&g_hist[recv[e]], 1);
}
__global__ void scan1_kernel() {
    __shared__ int s[1024];
    int t = threadIdx.x;
    int i = blockIdx.x * 1024 + t;
    int v = (i < N_NODES) ? g_hist[i] : 0;
    s[t] = v;
    __syncthreads();
    #pragma unroll
    for (int d = 1; d < 1024; d <<= 1) {
        int a = (t >= d) ? s[t - d] : 0;
        __syncthreads();
        s[t] += a;
        __syncthreads();
    }
    if (i < N_NODES) g_off[i] = s[t] - v;
    if (t == 1023) g_bsum[blockIdx.x] = s[t];
}
__global__ void scan2_kernel() {
    __shared__ int s[256];
    int t = threadIdx.x;
    int v = (t < SCAN_BLKS) ? g_bsum[t] : 0;
    s[t] = v;
    __syncthreads();
    #pragma unroll
    for (int d = 1; d < 256; d <<= 1) {
        int a = (t >= d) ? s[t - d] : 0;
        __syncthreads();
        s[t] += a;
        __syncthreads();
    }
    g_boff[t] = s[t] - v;
}
__global__ void scan3_kernel() {
    int i = blockIdx.x * 1024 + threadIdx.x;
    if (i < N_NODES) {
        int o = g_off[i] + g_boff[blockIdx.x];
        g_off[i] = o;
        g_cur[i] = o;
    }
    if (i == 0) g_off[N_NODES] = N_EDGES;
}
__global__ void fill_kernel(const int* __restrict__ recv) {
    int e = blockIdx.x * blockDim.x + threadIdx.x;
    if (e < N_EDGES) {
        int pos = atomicAdd(&g_cur[recv[e]], 1);
        g_elist[pos] = e;
    }
}

// ---------------------------------------------------------------------------
// Kernel 2b: gather-reduce edge rows -> agg in bf16 hi/lo. One warp/node.
// ---------------------------------------------------------------------------
__global__ __launch_bounds__(256) void gather_kernel(
    const float* __restrict__ edge_attr) {
    int warp = (blockIdx.x * 256 + threadIdx.x) >> 5;
    int lane = threadIdx.x & 31;
    if (warp >= N_NODES) return;
    int o0 = __ldg(&g_off[warp]);
    int o1 = __ldg(&g_off[warp + 1]);
    float4 a = make_float4(0.f, 0.f, 0.f, 0.f);
    int t = o0;
    for (; t + 4 <= o1; t += 4) {
        int e0 = __ldg(&g_elist[t + 0]);
        int e1 = __ldg(&g_elist[t + 1]);
        int e2 = __ldg(&g_elist[t + 2]);
        int e3 = __ldg(&g_elist[t + 3]);
        float4 v0 = *((const float4*)edge_attr + (size_t)e0 * 32 + lane);
        float4 v1 = *((const float4*)edge_attr + (size_t)e1 * 32 + lane);
        float4 v2 = *((const float4*)edge_attr + (size_t)e2 * 32 + lane);
        float4 v3 = *((const float4*)edge_attr + (size_t)e3 * 32 + lane);
        a.x += v0.x + v1.x + v2.x + v3.x;
        a.y += v0.y + v1.y + v2.y + v3.y;
        a.z += v0.z + v1.z + v2.z + v3.z;
        a.w += v0.w + v1.w + v2.w + v3.w;
    }
    for (; t < o1; ++t) {
        int e0 = __ldg(&g_elist[t]);
        float4 v0 = *((const float4*)edge_attr + (size_t)e0 * 32 + lane);
        a.x += v0.x; a.y += v0.y; a.z += v0.z; a.w += v0.w;
    }
    uint32_t h0, l0, h1, l1;
    split2(a.x, a.y, h0, l0);
    split2(a.z, a.w, h1, l1);
    ((uint2*)g_ahi)[(size_t)warp * 32 + lane] = make_uint2(h0, h1);
    ((uint2*)g_alo)[(size_t)warp * 32 + lane] = make_uint2(l0, l1);
}

// ---------------------------------------------------------------------------
// Kernel 3: persistent bf16 3-term MLP, direct bf16 cp.async, triple-buffer.
//   Barriers per tile: (1) x visible, (2) agg visible, (3) done reading G,
//   (4) H visible  (H columns are written by sibling warps of the M band!).
// ---------------------------------------------------------------------------
#define PITCH 136
#define AB_B  (128 * PITCH * 2)          // 34816
#define OFF_B1   (6 * AB_B)              // 208896
#define OFF_B2   (OFF_B1 + 512)
#define SMEM_SZ  (OFF_B2 + 512)          // 209920

__global__ __launch_bounds__(512, 1) void mma_mlp_kernel(
    const float* __restrict__ b1,
    const float* __restrict__ b2,
    float* __restrict__ out) {

    extern __shared__ char smem[];
    const uint32_t sb = smem_u32(smem);
    const int tid = threadIdx.x;
    const int lane = tid & 31;
    const int w = tid >> 5;
    const int mw = (w & 3) * 32;
    const int nwb = (w >> 2) * 4;        // n-block base (8-col blocks)

    float* sB1 = (float*)(smem + OFF_B1);
    float* sB2 = (float*)(smem + OFF_B2);
    if (tid < 128) { sB1[tid] = b1[tid]; sB2[tid] = b2[tid]; }

    const int arow = lane & 15;
    const int acol = (lane >> 4) * 8;
    const int gq = tid & 15;             // granule (16B = 8 bf16) in row
    const int grr = tid >> 4;            // row base 0..31

    uint32_t Xhi = sb + 0 * AB_B, Xlo = sb + 1 * AB_B;   // x(t), then H
    const uint32_t Ghi = sb + 2 * AB_B, Glo = sb + 3 * AB_B;  // agg(t)
    uint32_t Bhi = sb + 4 * AB_B, Blo = sb + 5 * AB_B;   // x(t+1)

    float acc[2][4][4];
    #pragma unroll
    for (int mt = 0; mt < 2; ++mt)
        #pragma unroll
        for (int nt = 0; nt < 4; ++nt)
            #pragma unroll
            for (int e = 0; e < 4; ++e) acc[mt][nt][e] = 0.f;

    auto load_tile = [&](const __nv_bfloat16* shi, const __nv_bfloat16* slo,
                         uint32_t dhi, uint32_t dlo, int node0, int V) {
        #pragma unroll
        for (int j = 0; j < 4; ++j) {
            int r = grr + j * 32;
            int rr = (r < V) ? r : (V - 1);
            size_t so = (size_t)(node0 + rr) * 128 + gq * 8;
            uint32_t doff = (uint32_t)(r * PITCH + gq * 8) * 2;
            cp_async16(dhi + doff, shi + so);
            cp_async16(dlo + doff, slo + so);
        }
        CP_COMMIT();
    };
    auto mma_step = [&](uint32_t ahiB, uint32_t aloB, const uint4* wf,
                        int ksg, int nks) {
        uint32_t ahi[2][4], alo[2][4];
        #pragma unroll
        for (int mt = 0; mt < 2; ++mt) {
            uint32_t aoff = (uint32_t)((mw + mt * 16 + arow) * PITCH +
                                       (ksg & 7) * 16 + acol) * 2;
            ldsm_x4(ahi[mt], ahiB + aoff);
            ldsm_x4(alo[mt], aloB + aoff);
        }
        #pragma unroll
        for (int nt = 0; nt < 4; ++nt) {
            uint4 f = __ldg(&wf[((nwb + nt) * nks + ksg) * 32 + lane]);
            #pragma unroll
            for (int mt = 0; mt < 2; ++mt) {
                mma_bf16(acc[mt][nt], ahi[mt], f.x, f.y);
                mma_bf16(acc[mt][nt], alo[mt], f.x, f.y);
                mma_bf16(acc[mt][nt], ahi[mt], f.z, f.w);
            }
        }
    };

    // prologue: commit group1 = x(t0), group2 = agg(t0)
    int tile = blockIdx.x;
    if (tile < NT) {
        int n0 = tile * 128, V0 = min(128, N_NODES - n0);
        load_tile(g_xhi, g_xlo, Xhi, Xlo, n0, V0);
        load_tile(g_ahi, g_alo, Ghi, Glo, n0, V0);
    }

    for (; tile < NT; tile += GRID_MLP) {
        const int node0 = tile * 128;
        const int V = min(128, N_NODES - node0);
        const int tile_n = tile + GRID_MLP;
        const int node0n = (tile_n < NT) ? tile_n * 128 : 0;
        const int Vn = (tile_n < NT) ? min(128, N_NODES - node0n) : 128;

        CP_WAIT1();            // x(t) landed (agg(t) may still be in flight)
        __syncthreads();       // x visible; all warps past GEMM2(t-1) on B
        load_tile(g_xhi, g_xlo, Bhi, Blo, node0n, Vn);   // x(t+1)

        #pragma unroll
        for (int ks = 0; ks < 8; ++ks)
            mma_step(Xhi, Xlo, g_W1f, ks, 16);

        CP_WAIT1();            // agg(t) landed (x(t+1) may be in flight)
        __syncthreads();       // agg visible
        #pragma unroll
        for (int ks = 0; ks < 8; ++ks)
            mma_step(Ghi, Glo, g_W1f, 8 + ks, 16);
        __syncthreads();       // all warps done reading G (and X)
        load_tile(g_ahi, g_alo, Ghi, Glo, node0n, Vn);   // agg(t+1)

        // Epilogue 1: H = relu(acc + b1) -> X buffers
        {
            const int r0 = lane >> 2;
            const int c0 = 2 * (lane & 3);
            #pragma unroll
            for (int mt = 0; mt < 2; ++mt) {
                #pragma unroll
                for (int nt = 0; nt < 4; ++nt) {
                    int c = nwb * 8 + nt * 8 + c0;
                    float bb0 = sB1[c], bb1 = sB1[c + 1];
                    int rA = mw + mt * 16 + r0;
                    float h00 = fmaxf(acc[mt][nt][0] + bb0, 0.f);
                    float h01 = fmaxf(acc[mt][nt][1] + bb1, 0.f);
                    float h10 = fmaxf(acc[mt][nt][2] + bb0, 0.f);
                    float h11 = fmaxf(acc[mt][nt][3] + bb1, 0.f);
                    uint32_t hp0, lp0, hp1, lp1;
                    split2(h00, h01, hp0, lp0);
                    split2(h10, h11, hp1, lp1);
                    uint32_t o0 = (uint32_t)(rA * PITCH + c) * 2;
                    uint32_t o1 = (uint32_t)((rA + 8) * PITCH + c) * 2;
                    asm volatile("st.shared.b32 [%0], %1;" :: "r"(Xhi + o0), "r"(hp0));
                    asm volatile("st.shared.b32 [%0], %1;" :: "r"(Xlo + o0), "r"(lp0));
                    asm volatile("st.shared.b32 [%0], %1;" :: "r"(Xhi + o1), "r"(hp1));
                    asm volatile("st.shared.b32 [%0], %1;" :: "r"(Xlo + o1), "r"(lp1));
                    #pragma unroll
                    for (int e = 0; e < 4; ++e) acc[mt][nt][e] = 0.f;
                }
            }
        }
        __syncthreads();       // H visible: columns come from sibling warps!

        // GEMM2 on H
        #pragma unroll
        for (int ks = 0; ks < 8; ++ks)
            mma_step(Xhi, Xlo, g_W2f, ks, 8);

        // Epilogue 2: out = acc + b2
        {
            const int r0 = lane >> 2;
            const int c0 = 2 * (lane & 3);
            #pragma unroll
            for (int mt = 0; mt < 2; ++mt) {
                #pragma unroll
                for (int nt = 0; nt < 4; ++nt) {
                    int c = nwb * 8 + nt * 8 + c0;
                    float bb0 = sB2[c], bb1 = sB2[c + 1];
                    int r = mw + mt * 16 + r0;
                    if (r < V)
                        *(float2*)(out + (size_t)(node0 + r) * 128 + c) =
                            make_float2(acc[mt][nt][0] + bb0, acc[mt][nt][1] + bb1);
                    if (r + 8 < V)
                        *(float2*)(out + (size_t)(node0 + r + 8) * 128 + c) =
                            make_float2(acc[mt][nt][2] + bb0, acc[mt][nt][3] + bb1);
                    #pragma unroll
                    for (int e = 0; e < 4; ++e) acc[mt][nt][e] = 0.f;
                }
            }
        }

        // rotate: B (holding x(t+1)) becomes X; old X becomes spare
        uint32_t th = Xhi, tl = Xlo;
        Xhi = Bhi; Xlo = Blo;
        Bhi = th;  Blo = tl;
    }
}

// ---------------------------------------------------------------------------
extern "C" void kernel_launch(void* const* d_in, const int* in_sizes, int n_in,
                              void* d_out, int out_size) {
    const float* x          = (const float*)d_in[0];
    const float* edge_attr  = (const float*)d_in[1];
    const int*   edge_index = (const int*)d_in[2];   // int32
    const float* W1         = (const float*)d_in[3];
    const float* b1         = (const float*)d_in[4];
    const float* W2         = (const float*)d_in[5];
    const float* b2         = (const float*)d_in[6];
    float*       out        = (float*)d_out;

    const int* recv = edge_index + N_EDGES;

    cudaFuncSetAttribute(mma_mlp_kernel,
                         cudaFuncAttributeMaxDynamicSharedMemorySize, SMEM_SZ);

    prep_w_kernel<<<32, 256>>>(W1, W2);
    prep_x_kernel<<<25000, 256>>>(x);
    zero_hist_kernel<<<SCAN_BLKS, 1024>>>();
    hist_kernel<<<3125, 256>>>(recv);
    scan1_kernel<<<SCAN_BLKS, 1024>>>();
    scan2_kernel<<<1, 256>>>();
    scan3_kernel<<<SCAN_BLKS, 1024>>>();
    fill_kernel<<<3125, 256>>>(recv);
    gather_kernel<<<25000, 256>>>(edge_attr);
    mma_mlp_kernel<<<GRID_MLP, 512, SMEM_SZ>>>(b1, b2, out);
}

// round 13
// speedup vs baseline: 2.7770x; 1.3628x over previous
#include <cuda_runtime.h>
#include <cuda_bf16.h>
#include <cstdint>

#define N_NODES 200000
#define N_EDGES 800000
#define D 128
#define NT 1563            // ceil(200000/128); last tile has 64 valid rows
#define GRID_MLP 148
#define SCAN_BLKS 196      // ceil(200000/1024)

// ---------------------------------------------------------------------------
// Device scratch (allocation-free rule).
// ---------------------------------------------------------------------------
__device__ float g_agg[(size_t)N_NODES * D];
// CSR for edge->receiver gather
__device__ int g_hist[N_NODES];
__device__ int g_off[N_NODES + 1];
__device__ int g_cur[N_NODES];
__device__ int g_elist[N_EDGES];
__device__ int g_bsum[256];
__device__ int g_boff[256];
// Fragment-major weights: uint4 = {hi_b0, hi_b1, lo_b0, lo_b1} per (nb, ks, lane)
__device__ uint4 g_W1f[16 * 16 * 32];   // [nb][ksg 0..15][lane]
__device__ uint4 g_W2f[16 * 8 * 32];    // [nb][ksg 0..7][lane]

// ---------------------------------------------------------------------------
// helpers
// ---------------------------------------------------------------------------
__device__ __forceinline__ uint32_t smem_u32(const void* p) {
    uint32_t a;
    asm("{ .reg .u64 t; cvta.to.shared.u64 t, %1; cvt.u32.u64 %0, t; }"
        : "=r"(a) : "l"(p));
    return a;
}
__device__ __forceinline__ uint32_t pack_bf16x2(float lo, float hi) {
    uint32_t r;
    asm("cvt.rn.bf16x2.f32 %0, %1, %2;" : "=r"(r) : "f"(hi), "f"(lo));
    return r;
}
__device__ __forceinline__ void split2(float v0, float v1,
                                       uint32_t& hp, uint32_t& lp) {
    hp = pack_bf16x2(v0, v1);
    float h0 = __uint_as_float(hp << 16);
    float h1 = __uint_as_float(hp & 0xffff0000u);
    lp = pack_bf16x2(v0 - h0, v1 - h1);
}
__device__ __forceinline__ void ldsm_x4(uint32_t (&r)[4], uint32_t addr) {
    asm volatile("ldmatrix.sync.aligned.m8n8.x4.shared.b16 {%0,%1,%2,%3}, [%4];"
                 : "=r"(r[0]), "=r"(r[1]), "=r"(r[2]), "=r"(r[3]) : "r"(addr));
}
__device__ __forceinline__ void mma_bf16(float (&d)[4], const uint32_t (&a)[4],
                                         uint32_t b0, uint32_t b1) {
    asm volatile(
        "mma.sync.aligned.m16n8k16.row.col.f32.bf16.bf16.f32 "
        "{%0,%1,%2,%3}, {%4,%5,%6,%7}, {%8,%9}, {%0,%1,%2,%3};"
        : "+f"(d[0]), "+f"(d[1]), "+f"(d[2]), "+f"(d[3])
        : "r"(a[0]), "r"(a[1]), "r"(a[2]), "r"(a[3]), "r"(b0), "r"(b1));
}
__device__ __forceinline__ void cp_async16(uint32_t dst, const void* src) {
    asm volatile("cp.async.ca.shared.global [%0], [%1], 16;"
                 :: "r"(dst), "l"(src) : "memory");
}
#define CP_COMMIT() asm volatile("cp.async.commit_group;" ::: "memory")
#define CP_WAIT0()  asm volatile("cp.async.wait_group 0;" ::: "memory")

// ---------------------------------------------------------------------------
// Kernel 0: fragment-major hi/lo bf16 weights.
// ---------------------------------------------------------------------------
__global__ void prep_w_kernel(const float* __restrict__ W1,
                              const float* __restrict__ W2) {
    int i = blockIdx.x * blockDim.x + threadIdx.x;
    if (i < 8192) {                       // W1: 16 nb x 16 ks x 32 lanes
        int lane = i & 31, ks = (i >> 5) & 15, nb = i >> 9;
        int n = nb * 8 + (lane >> 2);
        int k0 = ks * 16 + 2 * (lane & 3);
        float v00 = W1[(k0 + 0) * 128 + n], v01 = W1[(k0 + 1) * 128 + n];
        float v10 = W1[(k0 + 8) * 128 + n], v11 = W1[(k0 + 9) * 128 + n];
        uint32_t hb0, lb0, hb1, lb1;
        split2(v00, v01, hb0, lb0);
        split2(v10, v11, hb1, lb1);
        g_W1f[i] = make_uint4(hb0, hb1, lb0, lb1);
    }
    if (i < 4096) {                       // W2: 16 nb x 8 ks x 32 lanes
        int lane = i & 31, ks = (i >> 5) & 7, nb = i >> 8;
        int n = nb * 8 + (lane >> 2);
        int k0 = ks * 16 + 2 * (lane & 3);
        float v00 = W2[(k0 + 0) * 128 + n], v01 = W2[(k0 + 1) * 128 + n];
        float v10 = W2[(k0 + 8) * 128 + n], v11 = W2[(k0 + 9) * 128 + n];
        uint32_t hb0, lb0, hb1, lb1;
        split2(v00, v01, hb0, lb0);
        split2(v10, v11, hb1, lb1);
        g_W2f[i] = make_uint4(hb0, hb1, lb0, lb1);
    }
}

// ---------------------------------------------------------------------------
// CSR build: zero hist -> histogram -> scan -> fill.
// ---------------------------------------------------------------------------
__global__ void zero_hist_kernel() {
    int i = blockIdx.x * 1024 + threadIdx.x;
    if (i < N_NODES) g_hist[i] = 0;
}
__global__ void hist_kernel(const int* __restrict__ recv) {
    int e = blockIdx.x * blockDim.x + threadIdx.x;
    if (e < N_EDGES) atomicAdd(&g_hist[recv[e]], 1);
}
__global__ void scan1_kernel() {
    __shared__ int s[1024];
    int t = threadIdx.x;
    int i = blockIdx.x * 1024 + t;
    int v = (i < N_NODES) ? g_hist[i] : 0;
    s[t] = v;
    __syncthreads();
    #pragma unroll
    for (int d = 1; d < 1024; d <<= 1) {
        int a = (t >= d) ? s[t - d] : 0;
        __syncthreads();
        s[t] += a;
        __syncthreads();
    }
    if (i < N_NODES) g_off[i] = s[t] - v;
    if (t == 1023) g_bsum[blockIdx.x] = s[t];
}
__global__ void scan2_kernel() {
    __shared__ int s[256];
    int t = threadIdx.x;
    int v = (t < SCAN_BLKS) ? g_bsum[t] : 0;
    s[t] = v;
    __syncthreads();
    #pragma unroll
    for (int d = 1; d < 256; d <<= 1) {
        int a = (t >= d) ? s[t - d] : 0;
        __syncthreads();
        s[t] += a;
        __syncthreads();
    }
    g_boff[t] = s[t] - v;
}
__global__ void scan3_kernel() {
    int i = blockIdx.x * 1024 + threadIdx.x;
    if (i < N_NODES) {
        int o = g_off[i] + g_boff[blockIdx.x];
        g_off[i] = o;
        g_cur[i] = o;
    }
    if (i == 0) g_off[N_NODES] = N_EDGES;
}
__global__ void fill_kernel(const int* __restrict__ recv) {
    int e = blockIdx.x * blockDim.x + threadIdx.x;
    if (e < N_EDGES) {
        int pos = atomicAdd(&g_cur[recv[e]], 1);
        g_elist[pos] = e;
    }
}

// ---------------------------------------------------------------------------
// Kernel 2b: gather-reduce edge rows into g_agg. One warp per node.
// ---------------------------------------------------------------------------
__global__ __launch_bounds__(256) void gather_kernel(
    const float* __restrict__ edge_attr) {
    int warp = (blockIdx.x * 256 + threadIdx.x) >> 5;
    int lane = threadIdx.x & 31;
    if (warp >= N_NODES) return;
    int o0 = __ldg(&g_off[warp]);
    int o1 = __ldg(&g_off[warp + 1]);
    float4 a = make_float4(0.f, 0.f, 0.f, 0.f);
    int t = o0;
    for (; t + 4 <= o1; t += 4) {
        int e0 = __ldg(&g_elist[t + 0]);
        int e1 = __ldg(&g_elist[t + 1]);
        int e2 = __ldg(&g_elist[t + 2]);
        int e3 = __ldg(&g_elist[t + 3]);
        float4 v0 = *((const float4*)edge_attr + (size_t)e0 * 32 + lane);
        float4 v1 = *((const float4*)edge_attr + (size_t)e1 * 32 + lane);
        float4 v2 = *((const float4*)edge_attr + (size_t)e2 * 32 + lane);
        float4 v3 = *((const float4*)edge_attr + (size_t)e3 * 32 + lane);
        a.x += v0.x + v1.x + v2.x + v3.x;
        a.y += v0.y + v1.y + v2.y + v3.y;
        a.z += v0.z + v1.z + v2.z + v3.z;
        a.w += v0.w + v1.w + v2.w + v3.w;
    }
    for (; t < o1; ++t) {
        int e0 = __ldg(&g_elist[t]);
        float4 v0 = *((const float4*)edge_attr + (size_t)e0 * 32 + lane);
        a.x += v0.x; a.y += v0.y; a.z += v0.z; a.w += v0.w;
    }
    ((float4*)g_agg)[(size_t)warp * 32 + lane] = a;
}

// ---------------------------------------------------------------------------
// Kernel 3: persistent pipelined bf16 3-term MLP (R9 structure),
//   now 256 threads / 8 warps; warp tile 32(M) x 64(N) for register headroom
//   (256-reg cap lets ptxas hoist W-fragment LDGs across k-steps).
// ---------------------------------------------------------------------------
#define PITCH 136
#define AB_B  (128 * PITCH * 2)          // 34816
#define OFF_A0HI 0
#define OFF_A0LO (OFF_A0HI + AB_B)
#define OFF_A1HI (OFF_A0LO + AB_B)
#define OFF_A1LO (OFF_A1HI + AB_B)
#define OFF_STG  (OFF_A1LO + AB_B)       // fp32 128x128 = 65536
#define OFF_B1   (OFF_STG + 65536)
#define OFF_B2   (OFF_B1 + 512)
#define SMEM_SZ  (OFF_B2 + 512)          // 205824

__global__ __launch_bounds__(256, 1) void mma_mlp_kernel(
    const float* __restrict__ x,
    const float* __restrict__ b1,
    const float* __restrict__ b2,
    float* __restrict__ out) {

    extern __shared__ char smem[];
    const uint32_t sb = smem_u32(smem);
    const int tid = threadIdx.x;
    const int lane = tid & 31;
    const int w = tid >> 5;              // 8 warps
    const int mw = (w & 3) * 32;         // M band
    const int nwb = (w >> 2) * 8;        // n-block base: 0 or 8 (64 cols)

    float* sB1 = (float*)(smem + OFF_B1);
    float* sB2 = (float*)(smem + OFF_B2);
    if (tid < 128) { sB1[tid] = b1[tid]; sB2[tid] = b2[tid]; }

    const int arow = lane & 15;
    const int acol = (lane >> 4) * 8;
    const int gr = tid >> 5;             // 0..7
    const int gc = tid & 31;

    float acc[2][8][4];
    #pragma unroll
    for (int mt = 0; mt < 2; ++mt)
        #pragma unroll
        for (int nt = 0; nt < 8; ++nt)
            #pragma unroll
            for (int e = 0; e < 4; ++e) acc[mt][nt][e] = 0.f;

    auto stage_load = [&](const float* src, int node0, int V) {
        #pragma unroll
        for (int j = 0; j < 16; ++j) {
            int r = gr + j * 8;          // 0..127
            int rr = (r < V) ? r : (V - 1);
            cp_async16(sb + OFF_STG + (uint32_t)(r * 128 + gc * 4) * 4,
                       src + (size_t)(node0 + rr) * 128 + gc * 4);
        }
        CP_COMMIT();
    };
    auto convert_stage = [&](uint32_t dhi, uint32_t dlo) {
        #pragma unroll
        for (int j = 0; j < 16; ++j) {
            int r = gr + j * 8;
            float4 v = *(const float4*)(smem + OFF_STG + (r * 128 + gc * 4) * 4);
            uint32_t h0, l0, h1, l1;
            split2(v.x, v.y, h0, l0);
            split2(v.z, v.w, h1, l1);
            uint32_t off = (uint32_t)(r * PITCH + gc * 4) * 2;
            asm volatile("st.shared.v2.u32 [%0], {%1, %2};"
                         :: "r"(dhi + off), "r"(h0), "r"(h1));
            asm volatile("st.shared.v2.u32 [%0], {%1, %2};"
                         :: "r"(dlo + off), "r"(l0), "r"(l1));
        }
    };
    auto mma_step = [&](uint32_t ahiB, uint32_t aloB, const uint4* wf,
                        int ksg, int nks) {
        uint32_t ahi[2][4], alo[2][4];
        #pragma unroll
        for (int mt = 0; mt < 2; ++mt) {
            uint32_t aoff = (uint32_t)((mw + mt * 16 + arow) * PITCH +
                                       (ksg & 7) * 16 + acol) * 2;
            ldsm_x4(ahi[mt], ahiB + aoff);
            ldsm_x4(alo[mt], aloB + aoff);
        }
        // breadth-first W fragment loads (independent; hoistable)
        uint4 f[8];
        #pragma unroll
        for (int nt = 0; nt < 8; ++nt)
            f[nt] = __ldg(&wf[((nwb + nt) * nks + ksg) * 32 + lane]);
        #pragma unroll
        for (int nt = 0; nt < 8; ++nt) {
            #pragma unroll
            for (int mt = 0; mt < 2; ++mt) {
                mma_bf16(acc[mt][nt], ahi[mt], f[nt].x, f[nt].y);
                mma_bf16(acc[mt][nt], alo[mt], f[nt].x, f[nt].y);
                mma_bf16(acc[mt][nt], ahi[mt], f[nt].z, f[nt].w);
            }
        }
    };

    int tile = blockIdx.x;
    if (tile < NT) stage_load(x, tile * 128, min(128, N_NODES - tile * 128));
    __syncthreads();   // biases visible

    for (; tile < NT; tile += GRID_MLP) {
        const int node0 = tile * 128;
        const int V = min(128, N_NODES - node0);
        const int tile_n = tile + GRID_MLP;
        const int node0n = (tile_n < NT) ? tile_n * 128 : 0;
        const int Vn = (tile_n < NT) ? min(128, N_NODES - node0n) : 128;

        CP_WAIT0();
        convert_stage(sb + OFF_A0HI, sb + OFF_A0LO);
        stage_load(g_agg, node0, V);            // agg -> stage (async)
        __syncthreads();                        // A0 visible

        #pragma unroll
        for (int ks = 0; ks < 4; ++ks)
            mma_step(sb + OFF_A0HI, sb + OFF_A0LO, g_W1f, ks, 16);
        CP_WAIT0();
        convert_stage(sb + OFF_A1HI, sb + OFF_A1LO);
        stage_load(x, node0n, Vn);
        #pragma unroll
        for (int ks = 4; ks < 8; ++ks)
            mma_step(sb + OFF_A0HI, sb + OFF_A0LO, g_W1f, ks, 16);
        __syncthreads();                        // A1 visible

        #pragma unroll
        for (int ks = 0; ks < 8; ++ks)
            mma_step(sb + OFF_A1HI, sb + OFF_A1LO, g_W1f, 8 + ks, 16);

        // Epilogue 1: H = relu(acc + b1) -> A0 buffers
        {
            const int r0 = lane >> 2;
            const int c0 = 2 * (lane & 3);
            #pragma unroll
            for (int mt = 0; mt < 2; ++mt) {
                #pragma unroll
                for (int nt = 0; nt < 8; ++nt) {
                    int c = nwb * 8 + nt * 8 + c0;
                    float bb0 = sB1[c], bb1 = sB1[c + 1];
                    int rA = mw + mt * 16 + r0;
                    float h00 = fmaxf(acc[mt][nt][0] + bb0, 0.f);
                    float h01 = fmaxf(acc[mt][nt][1] + bb1, 0.f);
                    float h10 = fmaxf(acc[mt][nt][2] + bb0, 0.f);
                    float h11 = fmaxf(acc[mt][nt][3] + bb1, 0.f);
                    uint32_t hp0, lp0, hp1, lp1;
                    split2(h00, h01, hp0, lp0);
                    split2(h10, h11, hp1, lp1);
                    uint32_t o0 = (uint32_t)(rA * PITCH + c) * 2;
                    uint32_t o1 = (uint32_t)((rA + 8) * PITCH + c) * 2;
                    asm volatile("st.shared.b32 [%0], %1;" :: "r"(sb + OFF_A0HI + o0), "r"(hp0));
                    asm volatile("st.shared.b32 [%0], %1;" :: "r"(sb + OFF_A0LO + o0), "r"(lp0));
                    asm volatile("st.shared.b32 [%0], %1;" :: "r"(sb + OFF_A0HI + o1), "r"(hp1));
                    asm volatile("st.shared.b32 [%0], %1;" :: "r"(sb + OFF_A0LO + o1), "r"(lp1));
                    #pragma unroll
                    for (int e = 0; e < 4; ++e) acc[mt][nt][e] = 0.f;
                }
            }
        }
        __syncthreads();                        // H visible

        #pragma unroll
        for (int ks = 0; ks < 8; ++ks)
            mma_step(sb + OFF_A0HI, sb + OFF_A0LO, g_W2f, ks, 8);

        // Epilogue 2: out = acc + b2
        {
            const int r0 = lane >> 2;
            const int c0 = 2 * (lane & 3);
            #pragma unroll
            for (int mt = 0; mt < 2; ++mt) {
                #pragma unroll
                for (int nt = 0; nt < 8; ++nt) {
                    int c = nwb * 8 + nt * 8 + c0;
                    float bb0 = sB2[c], bb1 = sB2[c + 1];
                    int r = mw + mt * 16 + r0;
                    if (r < V)
                        *(float2*)(out + (size_t)(node0 + r) * 128 + c) =
                            make_float2(acc[mt][nt][0] + bb0, acc[mt][nt][1] + bb1);
                    if (r + 8 < V)
                        *(float2*)(out + (size_t)(node0 + r + 8) * 128 + c) =
                            make_float2(acc[mt][nt][2] + bb0, acc[mt][nt][3] + bb1);
                    #pragma unroll
                    for (int e = 0; e < 4; ++e) acc[mt][nt][e] = 0.f;
                }
            }
        }
        __syncthreads();   // all reads of A0/A1 done before next tile writes
    }
}

// ---------------------------------------------------------------------------
extern "C" void kernel_launch(void* const* d_in, const int* in_sizes, int n_in,
                              void* d_out, int out_size) {
    const float* x          = (const float*)d_in[0];
    const float* edge_attr  = (const float*)d_in[1];
    const int*   edge_index = (const int*)d_in[2];   // int32
    const float* W1         = (const float*)d_in[3];
    const float* b1         = (const float*)d_in[4];
    const float* W2         = (const float*)d_in[5];
    const float* b2         = (const float*)d_in[6];
    float*       out        = (float*)d_out;

    const int* recv = edge_index + N_EDGES;

    cudaFuncSetAttribute(mma_mlp_kernel,
                         cudaFuncAttributeMaxDynamicSharedMemorySize, SMEM_SZ);

    prep_w_kernel<<<32, 256>>>(W1, W2);
    zero_hist_kernel<<<SCAN_BLKS, 1024>>>();
    hist_kernel<<<3125, 256>>>(recv);
    scan1_kernel<<<SCAN_BLKS, 1024>>>();
    scan2_kernel<<<1, 256>>>();
    scan3_kernel<<<SCAN_BLKS, 1024>>>();
    fill_kernel<<<3125, 256>>>(recv);
    gather_kernel<<<25000, 256>>>(edge_attr);
    mma_mlp_kernel<<<GRID_MLP, 256, SMEM_SZ>>>(x, b1, b2, out);
}

// round 14
// speedup vs baseline: 2.8862x; 1.0393x over previous
#include <cuda_runtime.h>
#include <cuda_bf16.h>
#include <cstdint>

#define N_NODES 200000
#define N_EDGES 800000
#define D 128
#define NT64 3125          // 200000 / 64 exactly
#define GRID_MLP 148
#define NGROUPS 296        // 148 CTAs * 2 groups
#define SCAN_BLKS 196      // ceil(200000/1024)

// ---------------------------------------------------------------------------
// Device scratch (allocation-free rule).
// ---------------------------------------------------------------------------
__device__ float g_agg[(size_t)N_NODES * D];
// CSR for edge->receiver gather
__device__ int g_hist[N_NODES];
__device__ int g_off[N_NODES + 1];
__device__ int g_cur[N_NODES];
__device__ int g_elist[N_EDGES];
__device__ int g_bsum[256];
__device__ int g_boff[256];
// Fragment-major weights: uint4 = {hi_b0, hi_b1, lo_b0, lo_b1} per (nb, ks, lane)
__device__ uint4 g_W1f[16 * 16 * 32];   // [nb][ksg 0..15][lane]
__device__ uint4 g_W2f[16 * 8 * 32];    // [nb][ksg 0..7][lane]

// ---------------------------------------------------------------------------
// helpers
// ---------------------------------------------------------------------------
__device__ __forceinline__ uint32_t smem_u32(const void* p) {
    uint32_t a;
    asm("{ .reg .u64 t; cvta.to.shared.u64 t, %1; cvt.u32.u64 %0, t; }"
        : "=r"(a) : "l"(p));
    return a;
}
__device__ __forceinline__ uint32_t pack_bf16x2(float lo, float hi) {
    uint32_t r;
    asm("cvt.rn.bf16x2.f32 %0, %1, %2;" : "=r"(r) : "f"(hi), "f"(lo));
    return r;
}
__device__ __forceinline__ void split2(float v0, float v1,
                                       uint32_t& hp, uint32_t& lp) {
    hp = pack_bf16x2(v0, v1);
    float h0 = __uint_as_float(hp << 16);
    float h1 = __uint_as_float(hp & 0xffff0000u);
    lp = pack_bf16x2(v0 - h0, v1 - h1);
}
__device__ __forceinline__ void ldsm_x4(uint32_t (&r)[4], uint32_t addr) {
    asm volatile("ldmatrix.sync.aligned.m8n8.x4.shared.b16 {%0,%1,%2,%3}, [%4];"
                 : "=r"(r[0]), "=r"(r[1]), "=r"(r[2]), "=r"(r[3]) : "r"(addr));
}
__device__ __forceinline__ void mma_bf16(float (&d)[4], const uint32_t (&a)[4],
                                         uint32_t b0, uint32_t b1) {
    asm volatile(
        "mma.sync.aligned.m16n8k16.row.col.f32.bf16.bf16.f32 "
        "{%0,%1,%2,%3}, {%4,%5,%6,%7}, {%8,%9}, {%0,%1,%2,%3};"
        : "+f"(d[0]), "+f"(d[1]), "+f"(d[2]), "+f"(d[3])
        : "r"(a[0]), "r"(a[1]), "r"(a[2]), "r"(a[3]), "r"(b0), "r"(b1));
}
__device__ __forceinline__ void cp_async16(uint32_t dst, const void* src) {
    asm volatile("cp.async.ca.shared.global [%0], [%1], 16;"
                 :: "r"(dst), "l"(src) : "memory");
}
#define CP_COMMIT() asm volatile("cp.async.commit_group;" ::: "memory")
#define CP_WAIT0()  asm volatile("cp.async.wait_group 0;" ::: "memory")
#define BARG(id) asm volatile("bar.sync %0, 256;" :: "r"(id) : "memory")

// ---------------------------------------------------------------------------
// Kernel 0: fragment-major hi/lo bf16 weights.
// ---------------------------------------------------------------------------
__global__ void prep_w_kernel(const float* __restrict__ W1,
                              const float* __restrict__ W2) {
    int i = blockIdx.x * blockDim.x + threadIdx.x;
    if (i < 8192) {                       // W1: 16 nb x 16 ks x 32 lanes
        int lane = i & 31, ks = (i >> 5) & 15, nb = i >> 9;
        int n = nb * 8 + (lane >> 2);
        int k0 = ks * 16 + 2 * (lane & 3);
        float v00 = W1[(k0 + 0) * 128 + n], v01 = W1[(k0 + 1) * 128 + n];
        float v10 = W1[(k0 + 8) * 128 + n], v11 = W1[(k0 + 9) * 128 + n];
        uint32_t hb0, lb0, hb1, lb1;
        split2(v00, v01, hb0, lb0);
        split2(v10, v11, hb1, lb1);
        g_W1f[i] = make_uint4(hb0, hb1, lb0, lb1);
    }
    if (i < 4096) {                       // W2: 16 nb x 8 ks x 32 lanes
        int lane = i & 31, ks = (i >> 5) & 7, nb = i >> 8;
        int n = nb * 8 + (lane >> 2);
        int k0 = ks * 16 + 2 * (lane & 3);
        float v00 = W2[(k0 + 0) * 128 + n], v01 = W2[(k0 + 1) * 128 + n];
        float v10 = W2[(k0 + 8) * 128 + n], v11 = W2[(k0 + 9) * 128 + n];
        uint32_t hb0, lb0, hb1, lb1;
        split2(v00, v01, hb0, lb0);
        split2(v10, v11, hb1, lb1);
        g_W2f[i] = make_uint4(hb0, hb1, lb0, lb1);
    }
}

// ---------------------------------------------------------------------------
// CSR build: zero hist -> histogram -> scan -> fill.
// ---------------------------------------------------------------------------
__global__ void zero_hist_kernel() {
    int i = blockIdx.x * 1024 + threadIdx.x;
    if (i < N_NODES) g_hist[i] = 0;
}
__global__ void hist_kernel(const int* __restrict__ recv) {
    int e = blockIdx.x * blockDim.x + threadIdx.x;
    if (e < N_EDGES) atomicAdd(&g_hist[recv[e]], 1);
}
__global__ void scan1_kernel() {
    __shared__ int s[1024];
    int t = threadIdx.x;
    int i = blockIdx.x * 1024 + t;
    int v = (i < N_NODES) ? g_hist[i] : 0;
    s[t] = v;
    __syncthreads();
    #pragma unroll
    for (int d = 1; d < 1024; d <<= 1) {
        int a = (t >= d) ? s[t - d] : 0;
        __syncthreads();
        s[t] += a;
        __syncthreads();
    }
    if (i < N_NODES) g_off[i] = s[t] - v;
    if (t == 1023) g_bsum[blockIdx.x] = s[t];
}
__global__ void scan2_kernel() {
    __shared__ int s[256];
    int t = threadIdx.x;
    int v = (t < SCAN_BLKS) ? g_bsum[t] : 0;
    s[t] = v;
    __syncthreads();
    #pragma unroll
    for (int d = 1; d < 256; d <<= 1) {
        int a = (t >= d) ? s[t - d] : 0;
        __syncthreads();
        s[t] += a;
        __syncthreads();
    }
    g_boff[t] = s[t] - v;
}
__global__ void scan3_kernel() {
    int i = blockIdx.x * 1024 + threadIdx.x;
    if (i < N_NODES) {
        int o = g_off[i] + g_boff[blockIdx.x];
        g_off[i] = o;
        g_cur[i] = o;
    }
    if (i == 0) g_off[N_NODES] = N_EDGES;
}
__global__ void fill_kernel(const int* __restrict__ recv) {
    int e = blockIdx.x * blockDim.x + threadIdx.x;
    if (e < N_EDGES) {
        int pos = atomicAdd(&g_cur[recv[e]], 1);
        g_elist[pos] = e;
    }
}

// ---------------------------------------------------------------------------
// Kernel 2b: gather-reduce edge rows into g_agg. One warp per node.
// ---------------------------------------------------------------------------
__global__ __launch_bounds__(256) void gather_kernel(
    const float* __restrict__ edge_attr) {
    int warp = (blockIdx.x * 256 + threadIdx.x) >> 5;
    int lane = threadIdx.x & 31;
    if (warp >= N_NODES) return;
    int o0 = __ldg(&g_off[warp]);
    int o1 = __ldg(&g_off[warp + 1]);
    float4 a = make_float4(0.f, 0.f, 0.f, 0.f);
    int t = o0;
    for (; t + 4 <= o1; t += 4) {
        int e0 = __ldg(&g_elist[t + 0]);
        int e1 = __ldg(&g_elist[t + 1]);
        int e2 = __ldg(&g_elist[t + 2]);
        int e3 = __ldg(&g_elist[t + 3]);
        float4 v0 = *((const float4*)edge_attr + (size_t)e0 * 32 + lane);
        float4 v1 = *((const float4*)edge_attr + (size_t)e1 * 32 + lane);
        float4 v2 = *((const float4*)edge_attr + (size_t)e2 * 32 + lane);
        float4 v3 = *((const float4*)edge_attr + (size_t)e3 * 32 + lane);
        a.x += v0.x + v1.x + v2.x + v3.x;
        a.y += v0.y + v1.y + v2.y + v3.y;
        a.z += v0.z + v1.z + v2.z + v3.z;
        a.w += v0.w + v1.w + v2.w + v3.w;
    }
    for (; t < o1; ++t) {
        int e0 = __ldg(&g_elist[t]);
        float4 v0 = *((const float4*)edge_attr + (size_t)e0 * 32 + lane);
        a.x += v0.x; a.y += v0.y; a.z += v0.z; a.w += v0.w;
    }
    ((float4*)g_agg)[(size_t)warp * 32 + lane] = a;
}

// ---------------------------------------------------------------------------
// Kernel 3: split-CTA pipelined bf16 3-term MLP.
//   512 threads = 2 independent groups of 256 (8 warps each). Each group
//   processes its own stream of 64-node tiles with PRIVATE smem buffers and
//   group-local named barriers (bar.sync 1/2) -> the groups drift out of
//   phase, so one group's loads/epilogues overlap the other's HMMA stream.
//   Per group: warps 2(M) x 4(N), warp tile 32x32; GEMM1 K=256, GEMM2 K=128.
// ---------------------------------------------------------------------------
#define PITCH 136
#define AB64  (64 * PITCH * 2)           // 17408
#define GRP_B (4 * AB64 + 64 * 128 * 4)  // A0/A1 hi+lo + fp32 stage = 102400
#define OFF_STG (4 * AB64)
#define OFF_B1  (2 * GRP_B)              // 204800
#define OFF_B2  (OFF_B1 + 512)
#define SMEM_SZ (OFF_B2 + 512)           // 205824

__global__ __launch_bounds__(512, 1) void mma_mlp_kernel(
    const float* __restrict__ x,
    const float* __restrict__ b1,
    const float* __restrict__ b2,
    float* __restrict__ out) {

    extern __shared__ char smem[];
    const int tid = threadIdx.x;
    const int g = tid >> 8;              // group 0/1
    const int gtid = tid & 255;
    const int lane = tid & 31;
    const int wg = gtid >> 5;            // warp in group (0..7)
    const int mw = (wg & 1) * 32;        // M band within 64 rows
    const int nwb = (wg >> 1) * 4;       // n-block base (4 blocks of 8 cols)
    const int barid = g + 1;

    const uint32_t gb = smem_u32(smem) + g * GRP_B;
    const uint32_t A0HI = gb, A0LO = gb + AB64;
    const uint32_t A1HI = gb + 2 * AB64, A1LO = gb + 3 * AB64;
    const uint32_t STG = gb + OFF_STG - 0 + 0;  // gb + 4*AB64
    float* sB1 = (float*)(smem + OFF_B1);
    float* sB2 = (float*)(smem + OFF_B2);
    if (tid < 128) { sB1[tid] = b1[tid]; sB2[tid] = b2[tid]; }
    __syncthreads();   // biases visible to both groups (barrier 0, once)

    const int arow = lane & 15;
    const int acol = (lane >> 4) * 8;
    const int gr = gtid >> 5;            // 0..7
    const int gc = gtid & 31;

    float acc[2][4][4];
    #pragma unroll
    for (int mt = 0; mt < 2; ++mt)
        #pragma unroll
        for (int nt = 0; nt < 4; ++nt)
            #pragma unroll
            for (int e = 0; e < 4; ++e) acc[mt][nt][e] = 0.f;

    auto stage_load = [&](const float* src, int node0) {
        #pragma unroll
        for (int j = 0; j < 8; ++j) {
            int r = gr + j * 8;          // 0..63
            cp_async16(STG + (uint32_t)(r * 128 + gc * 4) * 4,
                       src + (size_t)(node0 + r) * 128 + gc * 4);
        }
        CP_COMMIT();
    };
    auto convert_stage = [&](uint32_t dhi, uint32_t dlo) {
        #pragma unroll
        for (int j = 0; j < 8; ++j) {
            int r = gr + j * 8;
            float4 v = *(const float4*)((const char*)smem +
                        (STG - smem_u32(smem)) + (r * 128 + gc * 4) * 4);
            uint32_t h0, l0, h1, l1;
            split2(v.x, v.y, h0, l0);
            split2(v.z, v.w, h1, l1);
            uint32_t off = (uint32_t)(r * PITCH + gc * 4) * 2;
            asm volatile("st.shared.v2.u32 [%0], {%1, %2};"
                         :: "r"(dhi + off), "r"(h0), "r"(h1));
            asm volatile("st.shared.v2.u32 [%0], {%1, %2};"
                         :: "r"(dlo + off), "r"(l0), "r"(l1));
        }
    };
    auto mma_step = [&](uint32_t ahiB, uint32_t aloB, const uint4* wf,
                        int ksg, int nks) {
        uint32_t ahi[2][4], alo[2][4];
        #pragma unroll
        for (int mt = 0; mt < 2; ++mt) {
            uint32_t aoff = (uint32_t)((mw + mt * 16 + arow) * PITCH +
                                       (ksg & 7) * 16 + acol) * 2;
            ldsm_x4(ahi[mt], ahiB + aoff);
            ldsm_x4(alo[mt], aloB + aoff);
        }
        #pragma unroll
        for (int nt = 0; nt < 4; ++nt) {
            uint4 f = __ldg(&wf[((nwb + nt) * nks + ksg) * 32 + lane]);
            #pragma unroll
            for (int mt = 0; mt < 2; ++mt) {
                mma_bf16(acc[mt][nt], ahi[mt], f.x, f.y);
                mma_bf16(acc[mt][nt], alo[mt], f.x, f.y);
                mma_bf16(acc[mt][nt], ahi[mt], f.z, f.w);
            }
        }
    };

    const int gg = blockIdx.x * 2 + g;   // global group id 0..295
    int tile = gg;
    stage_load(x, tile * 64);            // prologue: x(t0)

    for (; tile < NT64; tile += NGROUPS) {
        const int node0 = tile * 64;
        const int tile_n = tile + NGROUPS;
        const int node0n = (tile_n < NT64) ? tile_n * 64 : 0;

        CP_WAIT0();
        convert_stage(A0HI, A0LO);
        stage_load(g_agg, node0);               // agg -> stage (async)
        BARG(barid);                            // A0 visible

        #pragma unroll
        for (int ks = 0; ks < 4; ++ks)
            mma_step(A0HI, A0LO, g_W1f, ks, 16);
        CP_WAIT0();
        convert_stage(A1HI, A1LO);
        stage_load(x, node0n);                  // x(t+1)
        #pragma unroll
        for (int ks = 4; ks < 8; ++ks)
            mma_step(A0HI, A0LO, g_W1f, ks, 16);
        BARG(barid);                            // A1 visible

        #pragma unroll
        for (int ks = 0; ks < 8; ++ks)
            mma_step(A1HI, A1LO, g_W1f, 8 + ks, 16);

        // Epilogue 1: H = relu(acc + b1) -> A0 buffers
        {
            const int r0 = lane >> 2;
            const int c0 = 2 * (lane & 3);
            #pragma unroll
            for (int mt = 0; mt < 2; ++mt) {
                #pragma unroll
                for (int nt = 0; nt < 4; ++nt) {
                    int c = nwb * 8 + nt * 8 + c0;
                    float bb0 = sB1[c], bb1 = sB1[c + 1];
                    int rA = mw + mt * 16 + r0;
                    float h00 = fmaxf(acc[mt][nt][0] + bb0, 0.f);
                    float h01 = fmaxf(acc[mt][nt][1] + bb1, 0.f);
                    float h10 = fmaxf(acc[mt][nt][2] + bb0, 0.f);
                    float h11 = fmaxf(acc[mt][nt][3] + bb1, 0.f);
                    uint32_t hp0, lp0, hp1, lp1;
                    split2(h00, h01, hp0, lp0);
                    split2(h10, h11, hp1, lp1);
                    uint32_t o0 = (uint32_t)(rA * PITCH + c) * 2;
                    uint32_t o1 = (uint32_t)((rA + 8) * PITCH + c) * 2;
                    asm volatile("st.shared.b32 [%0], %1;" :: "r"(A0HI + o0), "r"(hp0));
                    asm volatile("st.shared.b32 [%0], %1;" :: "r"(A0LO + o0), "r"(lp0));
                    asm volatile("st.shared.b32 [%0], %1;" :: "r"(A0HI + o1), "r"(hp1));
                    asm volatile("st.shared.b32 [%0], %1;" :: "r"(A0LO + o1), "r"(lp1));
                    #pragma unroll
                    for (int e = 0; e < 4; ++e) acc[mt][nt][e] = 0.f;
                }
            }
        }
        BARG(barid);                            // H visible (cross-warp cols)

        #pragma unroll
        for (int ks = 0; ks < 8; ++ks)
            mma_step(A0HI, A0LO, g_W2f, ks, 8);

        // Epilogue 2: out = acc + b2  (tiles are always full: V = 64)
        {
            const int r0 = lane >> 2;
            const int c0 = 2 * (lane & 3);
            #pragma unroll
            for (int mt = 0; mt < 2; ++mt) {
                #pragma unroll
                for (int nt = 0; nt < 4; ++nt) {
                    int c = nwb * 8 + nt * 8 + c0;
                    float bb0 = sB2[c], bb1 = sB2[c + 1];
                    int r = mw + mt * 16 + r0;
                    *(float2*)(out + (size_t)(node0 + r) * 128 + c) =
                        make_float2(acc[mt][nt][0] + bb0, acc[mt][nt][1] + bb1);
                    *(float2*)(out + (size_t)(node0 + r + 8) * 128 + c) =
                        make_float2(acc[mt][nt][2] + bb0, acc[mt][nt][3] + bb1);
                    #pragma unroll
                    for (int e = 0; e < 4; ++e) acc[mt][nt][e] = 0.f;
                }
            }
        }
        BARG(barid);   // all reads of A0/A1 done before next tile writes
    }
}

// ---------------------------------------------------------------------------
extern "C" void kernel_launch(void* const* d_in, const int* in_sizes, int n_in,
                              void* d_out, int out_size) {
    const float* x          = (const float*)d_in[0];
    const float* edge_attr  = (const float*)d_in[1];
    const int*   edge_index = (const int*)d_in[2];   // int32
    const float* W1         = (const float*)d_in[3];
    const float* b1         = (const float*)d_in[4];
    const float* W2         = (const float*)d_in[5];
    const float* b2         = (const float*)d_in[6];
    float*       out        = (float*)d_out;

    const int* recv = edge_index + N_EDGES;

    cudaFuncSetAttribute(mma_mlp_kernel,
                         cudaFuncAttributeMaxDynamicSharedMemorySize, SMEM_SZ);

    prep_w_kernel<<<32, 256>>>(W1, W2);
    zero_hist_kernel<<<SCAN_BLKS, 1024>>>();
    hist_kernel<<<3125, 256>>>(recv);
    scan1_kernel<<<SCAN_BLKS, 1024>>>();
    scan2_kernel<<<1, 256>>>();
    scan3_kernel<<<SCAN_BLKS, 1024>>>();
    fill_kernel<<<3125, 256>>>(recv);
    gather_kernel<<<25000, 256>>>(edge_attr);
    mma_mlp_kernel<<<GRID_MLP, 512, SMEM_SZ>>>(x, b1, b2, out);
}